// round 4
// baseline (speedup 1.0000x reference)
#include <cuda_runtime.h>
#include <cstdint>

// ---------------------------------------------------------------------------
// GCN via CSR-gather:
//   p = (x @ W1) * dinv
//   gather1: q[n] = dinv*(dinv*(sum_{s in nbr(n)} p[s] + p[n]) + b1)
//   gather2: h[n] = dinv*(sum q[s] + q[n]);  pool[batch[n]] += h  (red.v4)
//   head: mean, @W2+b2, relu(@fcW1+fcb1), batchnorm, softplus(@fcW2+fcb2)
// ---------------------------------------------------------------------------

#define MAXN 100000
#define MAXE 1600000
#define MAXG 256
#define C 32

__device__ int   g_csr[MAXE];
__device__ int   g_deg[MAXN];
__device__ int   g_off[MAXN];
__device__ int   g_cur[MAXN];
__device__ float g_dinv[MAXN];
__device__ float g_p[MAXN * C];
__device__ float g_q[MAXN * C];
__device__ float g_pool[MAXG * C];
__device__ int   g_flags[2];        // [0]=edge_index int64, [1]=batch int64
__device__ int   g_part[256];
__device__ int   g_done;

static inline int ceil_div(int a, int b) { return (a + b - 1) / b; }

__device__ __forceinline__ int idx_get(const void* p, long i, int is64) {
    return is64 ? (int)((const long long*)p)[i] : ((const int*)p)[i];
}

// ---------------------------------------------------------------------------
// init: zero deg/pool/done; block 0 detects index dtypes
// ---------------------------------------------------------------------------
__global__ void k_init(const unsigned* __restrict__ e, long ewords,
                       const unsigned* __restrict__ b, long bwords,
                       int N, int G) {
    int stride = gridDim.x * blockDim.x;
    int t = blockIdx.x * blockDim.x + threadIdx.x;
    for (int i = t; i < N; i += stride) g_deg[i] = 0;
    for (int i = t; i < G * C; i += stride) g_pool[i] = 0.0f;
    if (t == 0) g_done = 0;

    if (blockIdx.x == 0) {
        __shared__ unsigned se, sb;
        if (threadIdx.x == 0) { se = 0u; sb = 0u; }
        __syncthreads();
        unsigned a = 0u, c = 0u;
        long eh = ewords / 2, bh = bwords / 2;
        for (int s = 0; s < 16; s++) {
            long idx = (long)(threadIdx.x * 16 + s);
            long j = (idx * eh) / 4096;
            a |= e[2 * j + 1];
            long k = (idx * bh) / 4096;
            c |= b[2 * k + 1];
        }
        atomicOr(&se, a);
        atomicOr(&sb, c);
        __syncthreads();
        if (threadIdx.x == 0) {
            g_flags[0] = (se == 0u) ? 1 : 0;
            g_flags[1] = (sb == 0u) ? 1 : 0;
        }
    }
}

// ---------------------------------------------------------------------------
// degree count: 8 edges/thread, warp-coalesced, independent REDs
// ---------------------------------------------------------------------------
__global__ void k_deg(const void* __restrict__ eidx, int E) {
    int is64 = g_flags[0];
    int warp = (blockIdx.x * blockDim.x + threadIdx.x) >> 5;
    int lane = threadIdx.x & 31;
    int base = warp * 256 + lane;

    int tgt[8];
    int cnt = 0;
#pragma unroll
    for (int u = 0; u < 8; u++) {
        int e = base + 32 * u;
        if (e < E) { tgt[cnt++] = idx_get(eidx, (long)E + e, is64); }
    }
#pragma unroll
    for (int u = 0; u < 8; u++) {
        if (u < cnt) atomicAdd(&g_deg[tgt[u]], 1);
    }
}

// ---------------------------------------------------------------------------
// single-pass exclusive scan (<=98 co-resident blocks, publish+spin)
// ---------------------------------------------------------------------------
__global__ void k_scan(int N) {
    __shared__ int warp_sums[32];
    __shared__ int block_prefix_sh;

    int t = threadIdx.x;
    int i = blockIdx.x * 1024 + t;
    int d = (i < N) ? g_deg[i] : 0;

    int v = d;
#pragma unroll
    for (int o = 1; o < 32; o <<= 1) {
        int u = __shfl_up_sync(0xFFFFFFFFu, v, o);
        if ((t & 31) >= o) v += u;
    }
    if ((t & 31) == 31) warp_sums[t >> 5] = v;
    __syncthreads();
    if (t < 32) {
        int w = warp_sums[t];
#pragma unroll
        for (int o = 1; o < 32; o <<= 1) {
            int u = __shfl_up_sync(0xFFFFFFFFu, w, o);
            if (t >= o) w += u;
        }
        warp_sums[t] = w;
    }
    __syncthreads();
    int warp_base = (t >= 32) ? warp_sums[(t >> 5) - 1] : 0;
    int excl_local = warp_base + v - d;
    int block_total = warp_sums[31];

    if (t == 0) {
        g_part[blockIdx.x] = block_total;
        __threadfence();
        atomicAdd(&g_done, 1);
        while (atomicAdd(&g_done, 0) < (int)gridDim.x) { }
        int pre = 0;
        for (int bb = 0; bb < (int)blockIdx.x; bb++) pre += g_part[bb];
        block_prefix_sh = pre;
    }
    __syncthreads();
    int excl = block_prefix_sh + excl_local;

    if (i < N) {
        g_off[i] = excl;
        g_cur[i] = excl;
        g_dinv[i] = rsqrtf(1.0f + (float)d);
    }
}

// ---------------------------------------------------------------------------
// CSR placement: 8 edges/thread, batched loads -> 8 independent atomics
// ---------------------------------------------------------------------------
__global__ void k_place(const void* __restrict__ eidx, int E) {
    int is64 = g_flags[0];
    int warp = (blockIdx.x * blockDim.x + threadIdx.x) >> 5;
    int lane = threadIdx.x & 31;
    int base = warp * 256 + lane;

    int src[8], tgt[8];
    int cnt = 0;
#pragma unroll
    for (int u = 0; u < 8; u++) {
        int e = base + 32 * u;
        if (e < E) {
            src[cnt] = idx_get(eidx, e, is64);
            tgt[cnt] = idx_get(eidx, (long)E + e, is64);
            cnt++;
        }
    }
    int slot[8];
#pragma unroll
    for (int u = 0; u < 8; u++) {
        if (u < cnt) slot[u] = atomicAdd(&g_cur[tgt[u]], 1);
    }
#pragma unroll
    for (int u = 0; u < 8; u++) {
        if (u < cnt) g_csr[slot[u]] = src[u];
    }
}

// ---------------------------------------------------------------------------
// GEMM1 with packed fma.rn.f32x2: p[n,:] = dinv[n] * (x[n,:] @ W1)
// ---------------------------------------------------------------------------
__global__ void __launch_bounds__(256) k_gemm1(const float* __restrict__ x,
                                               const float* __restrict__ W1, int N) {
    __shared__ unsigned long long sW[128 * 16];
    const unsigned long long* Wp = (const unsigned long long*)W1;
    for (int i = threadIdx.x; i < 128 * 16; i += 256) sW[i] = Wp[i];
    __syncthreads();

    int n = blockIdx.x * 256 + threadIdx.x;
    if (n >= N) return;

    unsigned long long acc[16];
#pragma unroll
    for (int j = 0; j < 16; j++) acc[j] = 0ull;

    const float4* xr = (const float4*)(x + (size_t)n * 128);
#pragma unroll 2
    for (int k4 = 0; k4 < 32; k4++) {
        float4 xv = __ldg(&xr[k4]);
        const float* xf = (const float*)&xv;
#pragma unroll
        for (int kk = 0; kk < 4; kk++) {
            unsigned xb = __float_as_uint(xf[kk]);
            unsigned long long xx;
            asm("mov.b64 %0, {%1, %1};" : "=l"(xx) : "r"(xb));
            const unsigned long long* wr = sW + (k4 * 4 + kk) * 16;
#pragma unroll
            for (int j = 0; j < 16; j++) {
                asm("fma.rn.f32x2 %0, %1, %2, %0;"
                    : "+l"(acc[j]) : "l"(xx), "l"(wr[j]));
            }
        }
    }

    float di = g_dinv[n];
    float* out = g_p + (size_t)n * C;
#pragma unroll
    for (int j = 0; j < 16; j++) {
        unsigned lo, hi;
        asm("mov.b64 {%0, %1}, %2;" : "=r"(lo), "=r"(hi) : "l"(acc[j]));
        out[2 * j]     = __uint_as_float(lo) * di;
        out[2 * j + 1] = __uint_as_float(hi) * di;
    }
}

// ---------------------------------------------------------------------------
// Gather layer 1: one warp per node, lane = feature column, unroll 8 edges.
// ---------------------------------------------------------------------------
__global__ void __launch_bounds__(256) k_gather1(const float* __restrict__ b1, int N) {
    int node = blockIdx.x * 8 + (threadIdx.x >> 5);
    int lane = threadIdx.x & 31;
    if (node >= N) return;

    int beg = g_off[node];
    int end = beg + g_deg[node];

    const float* P = g_p;
    float a0 = __ldg(&P[(size_t)node * C + lane]);  // self-loop
    float a1 = 0.0f, a2 = 0.0f, a3 = 0.0f;

    int e = beg;
    for (; e + 8 <= end; e += 8) {
        int i0 = g_csr[e + 0], i1 = g_csr[e + 1], i2 = g_csr[e + 2], i3 = g_csr[e + 3];
        int i4 = g_csr[e + 4], i5 = g_csr[e + 5], i6 = g_csr[e + 6], i7 = g_csr[e + 7];
        float v0 = __ldg(&P[(size_t)i0 * C + lane]);
        float v1 = __ldg(&P[(size_t)i1 * C + lane]);
        float v2 = __ldg(&P[(size_t)i2 * C + lane]);
        float v3 = __ldg(&P[(size_t)i3 * C + lane]);
        float v4 = __ldg(&P[(size_t)i4 * C + lane]);
        float v5 = __ldg(&P[(size_t)i5 * C + lane]);
        float v6 = __ldg(&P[(size_t)i6 * C + lane]);
        float v7 = __ldg(&P[(size_t)i7 * C + lane]);
        a0 += v0; a1 += v1; a2 += v2; a3 += v3;
        a0 += v4; a1 += v5; a2 += v6; a3 += v7;
    }
    for (; e < end; e++) {
        a0 += __ldg(&P[(size_t)g_csr[e] * C + lane]);
    }
    float acc = (a0 + a1) + (a2 + a3);

    float di = g_dinv[node];
    float q = di * (di * acc + __ldg(&b1[lane]));
    g_q[(size_t)node * C + lane] = q;
}

// ---------------------------------------------------------------------------
// Gather layer 2 + fused pooling (shfl-pack to float4 REDs on lanes 0-7)
// ---------------------------------------------------------------------------
__device__ __forceinline__ void red_add_v4(float* ptr, float4 v) {
    asm volatile("red.global.add.v4.f32 [%0], {%1, %2, %3, %4};"
                 :: "l"(ptr), "f"(v.x), "f"(v.y), "f"(v.z), "f"(v.w)
                 : "memory");
}

__global__ void __launch_bounds__(256) k_gather2(const void* __restrict__ batch, int N) {
    int node = blockIdx.x * 8 + (threadIdx.x >> 5);
    int lane = threadIdx.x & 31;
    if (node >= N) return;

    int beg = g_off[node];
    int end = beg + g_deg[node];

    const float* Q = g_q;
    float a0 = __ldg(&Q[(size_t)node * C + lane]);  // self-loop
    float a1 = 0.0f, a2 = 0.0f, a3 = 0.0f;

    int e = beg;
    for (; e + 8 <= end; e += 8) {
        int i0 = g_csr[e + 0], i1 = g_csr[e + 1], i2 = g_csr[e + 2], i3 = g_csr[e + 3];
        int i4 = g_csr[e + 4], i5 = g_csr[e + 5], i6 = g_csr[e + 6], i7 = g_csr[e + 7];
        float v0 = __ldg(&Q[(size_t)i0 * C + lane]);
        float v1 = __ldg(&Q[(size_t)i1 * C + lane]);
        float v2 = __ldg(&Q[(size_t)i2 * C + lane]);
        float v3 = __ldg(&Q[(size_t)i3 * C + lane]);
        float v4 = __ldg(&Q[(size_t)i4 * C + lane]);
        float v5 = __ldg(&Q[(size_t)i5 * C + lane]);
        float v6 = __ldg(&Q[(size_t)i6 * C + lane]);
        float v7 = __ldg(&Q[(size_t)i7 * C + lane]);
        a0 += v0; a1 += v1; a2 += v2; a3 += v3;
        a0 += v4; a1 += v5; a2 += v6; a3 += v7;
    }
    for (; e < end; e++) {
        a0 += __ldg(&Q[(size_t)g_csr[e] * C + lane]);
    }
    float acc = (a0 + a1) + (a2 + a3);

    float h = g_dinv[node] * acc;

    // pack 4 consecutive lanes' scalars into float4 on lanes 0-7
    unsigned m = 0xFFFFFFFFu;
    int sbase = (lane * 4) & 31;
    float px = __shfl_sync(m, h, sbase + 0);
    float py = __shfl_sync(m, h, sbase + 1);
    float pz = __shfl_sync(m, h, sbase + 2);
    float pw = __shfl_sync(m, h, sbase + 3);

    int gidx = idx_get(batch, node, g_flags[1]);
    if (lane < 8) {
        red_add_v4(g_pool + (size_t)gidx * C + lane * 4, make_float4(px, py, pz, pw));
    }
}

// ---------------------------------------------------------------------------
// Head (1 block, 1 thread/graph)
// ---------------------------------------------------------------------------
__global__ void k_head(const void* __restrict__ batch, int N,
                       const float* __restrict__ W2, const float* __restrict__ b2,
                       const float* __restrict__ fcW1, const float* __restrict__ fcb1,
                       const float* __restrict__ gamma, const float* __restrict__ beta,
                       const float* __restrict__ fcW2, const float* __restrict__ fcb2,
                       float* __restrict__ out, int G) {
    __shared__ float sW2[32 * 64];
    __shared__ float sF1[64 * 32];
    __shared__ float sb2[64], sfb1[32], sgam[32], sbet[32], sfw2[32];
    __shared__ float ssum[32], ssq[32];
    __shared__ float sfb2;

    int tid = threadIdx.x;
    for (int i = tid; i < 32 * 64; i += blockDim.x) sW2[i] = W2[i];
    for (int i = tid; i < 64 * 32; i += blockDim.x) sF1[i] = fcW1[i];
    if (tid < 64) sb2[tid] = b2[tid];
    if (tid < 32) {
        sfb1[tid] = fcb1[tid]; sgam[tid] = gamma[tid]; sbet[tid] = beta[tid];
        sfw2[tid] = fcW2[tid]; ssum[tid] = 0.0f; ssq[tid] = 0.0f;
    }
    if (tid == 0) sfb2 = fcb2[0];
    __syncthreads();

    int g = tid;
    int is64 = g_flags[1];

    int lo = 0, hi = N;
    while (lo < hi) { int m = (lo + hi) >> 1; if (idx_get(batch, m, is64) < g) lo = m + 1; else hi = m; }
    int start = lo;
    hi = N;
    while (lo < hi) { int m = (lo + hi) >> 1; if (idx_get(batch, m, is64) < g + 1) lo = m + 1; else hi = m; }
    int cnt = lo - start;
    float inv_cnt = 1.0f / (float)max(cnt, 1);

    float r[32];
#pragma unroll
    for (int i = 0; i < 32; i++) r[i] = g_pool[g * 32 + i] * inv_cnt;

    float o2[64];
#pragma unroll
    for (int j = 0; j < 64; j++) o2[j] = sb2[j];
    for (int k = 0; k < 32; k++) {
        float rk = r[k];
#pragma unroll
        for (int j = 0; j < 64; j++) o2[j] = fmaf(rk, sW2[k * 64 + j], o2[j]);
    }

    float z[32];
#pragma unroll
    for (int i = 0; i < 32; i++) z[i] = sfb1[i];
    for (int j = 0; j < 64; j++) {
        float oj = o2[j];
#pragma unroll
        for (int i = 0; i < 32; i++) z[i] = fmaf(oj, sF1[j * 32 + i], z[i]);
    }
#pragma unroll
    for (int i = 0; i < 32; i++) z[i] = fmaxf(z[i], 0.0f);

    for (int i = 0; i < 32; i++) {
        float v = z[i], v2 = v * v;
#pragma unroll
        for (int o = 16; o > 0; o >>= 1) {
            v += __shfl_down_sync(0xFFFFFFFFu, v, o);
            v2 += __shfl_down_sync(0xFFFFFFFFu, v2, o);
        }
        if ((tid & 31) == 0) { atomicAdd(&ssum[i], v); atomicAdd(&ssq[i], v2); }
    }
    __syncthreads();

    float acc = sfb2;
    float invG = 1.0f / (float)G;
#pragma unroll
    for (int i = 0; i < 32; i++) {
        float mu = ssum[i] * invG;
        float var = ssq[i] * invG - mu * mu;
        float zb = (z[i] - mu) * rsqrtf(var + 1e-5f) * sgam[i] + sbet[i];
        acc = fmaf(zb, sfw2[i], acc);
    }
    out[g] = fmaxf(acc, 0.0f) + log1pf(expf(-fabsf(acc)));
}

// ---------------------------------------------------------------------------
extern "C" void kernel_launch(void* const* d_in, const int* in_sizes, int n_in,
                              void* d_out, int out_size) {
    const float* x     = (const float*)d_in[0];
    const void*  eidx  = d_in[1];
    const void*  batch = d_in[2];
    const float* W1    = (const float*)d_in[3];
    const float* b1    = (const float*)d_in[4];
    const float* W2    = (const float*)d_in[5];
    const float* b2    = (const float*)d_in[6];
    const float* fcW1  = (const float*)d_in[7];
    const float* fcb1  = (const float*)d_in[8];
    const float* gamma = (const float*)d_in[9];
    const float* beta  = (const float*)d_in[10];
    const float* fcW2  = (const float*)d_in[11];
    const float* fcb2  = (const float*)d_in[12];

    int N = in_sizes[0] / 128;
    int E = in_sizes[1] / 2;
    int G = out_size;

    k_init<<<128, 256>>>((const unsigned*)eidx, (long)2 * E,
                         (const unsigned*)batch, (long)N, N, G);
    k_deg<<<ceil_div(E, 2048), 256>>>(eidx, E);
    k_scan<<<ceil_div(N, 1024), 1024>>>(N);
    k_place<<<ceil_div(E, 2048), 256>>>(eidx, E);
    k_gemm1<<<ceil_div(N, 256), 256>>>(x, W1, N);
    k_gather1<<<ceil_div(N, 8), 256>>>(b1, N);
    k_gather2<<<ceil_div(N, 8), 256>>>(batch, N);
    k_head<<<1, G>>>(batch, N, W2, b2, fcW1, fcb1, gamma, beta, fcW2, fcb2,
                     (float*)d_out, G);
}

// round 5
// speedup vs baseline: 1.2557x; 1.2557x over previous
#include <cuda_runtime.h>
#include <cstdint>

// ---------------------------------------------------------------------------
// GCN via one-pass bucket-CSR gather:
//   place:   bucket[dst*64+slot]=src (slot via atomic); cur[dst] ends as degree
//   gemm1:   dinv=rsqrt(1+deg); p = (x @ W1) * dinv
//   gather1: q[n] = dinv*(dinv*(sum_{s in nbr(n)} p[s] + p[n]) + b1)
//   gather2: h[n] = dinv*(sum q[s] + q[n]); pool[batch[n]] += h (red.v4)
//   head:    mean, @W2+b2, relu(@fcW1+fcb1), batchnorm, softplus(@fcW2+fcb2)
// Overflow (deg > 64) goes to an exact side list handled in the gathers.
// ---------------------------------------------------------------------------

#define MAXN 100000
#define MAXE 1600000
#define MAXG 256
#define C 32
#define CAP 64

__device__ int   g_bucket[MAXN * CAP];
__device__ int   g_cur[MAXN];          // placement cursor == degree afterwards
__device__ int   g_ovf_dst[MAXE];
__device__ int   g_ovf_src[MAXE];
__device__ int   g_ovf_cnt;
__device__ float g_dinv[MAXN];
__device__ float g_p[MAXN * C];
__device__ float g_q[MAXN * C];
__device__ float g_pool[MAXG * C];
__device__ int   g_flags[2];           // [0]=edge_index int64, [1]=batch int64

static inline int ceil_div(int a, int b) { return (a + b - 1) / b; }

__device__ __forceinline__ int idx_get(const void* p, long i, int is64) {
    return is64 ? (int)((const long long*)p)[i] : ((const int*)p)[i];
}

// ---------------------------------------------------------------------------
// init: zero cur/pool/ovf_cnt; block 0 detects index dtypes
// (positive int64 => every odd 32-bit word is zero; sample 4096 odd words)
// ---------------------------------------------------------------------------
__global__ void k_init(const unsigned* __restrict__ e, long ewords,
                       const unsigned* __restrict__ b, long bwords,
                       int N, int G) {
    int stride = gridDim.x * blockDim.x;
    int t = blockIdx.x * blockDim.x + threadIdx.x;
    for (int i = t; i < N; i += stride) g_cur[i] = 0;
    for (int i = t; i < G * C; i += stride) g_pool[i] = 0.0f;
    if (t == 0) g_ovf_cnt = 0;

    if (blockIdx.x == 0) {
        __shared__ unsigned se, sb;
        if (threadIdx.x == 0) { se = 0u; sb = 0u; }
        __syncthreads();
        unsigned a = 0u, c = 0u;
        long eh = ewords / 2, bh = bwords / 2;
        for (int s = 0; s < 16; s++) {
            long idx = (long)(threadIdx.x * 16 + s);
            long j = (idx * eh) / 4096;
            a |= e[2 * j + 1];
            long k = (idx * bh) / 4096;
            c |= b[2 * k + 1];
        }
        atomicOr(&se, a);
        atomicOr(&sb, c);
        __syncthreads();
        if (threadIdx.x == 0) {
            g_flags[0] = (se == 0u) ? 1 : 0;
            g_flags[1] = (sb == 0u) ? 1 : 0;
        }
    }
}

// ---------------------------------------------------------------------------
// One-pass bucket placement; g_cur ends as full degree.
// ---------------------------------------------------------------------------
__global__ void k_place(const void* __restrict__ eidx, int E) {
    int is64 = g_flags[0];
    int stride = gridDim.x * blockDim.x;
    for (int ee = blockIdx.x * blockDim.x + threadIdx.x; ee < E; ee += stride) {
        int s = idx_get(eidx, ee, is64);
        int t = idx_get(eidx, (long)E + ee, is64);
        int slot = atomicAdd(&g_cur[t], 1);
        if (slot < CAP) {
            g_bucket[(size_t)t * CAP + slot] = s;
        } else {
            int o = atomicAdd(&g_ovf_cnt, 1);
            g_ovf_dst[o] = t;
            g_ovf_src[o] = s;
        }
    }
}

// ---------------------------------------------------------------------------
// GEMM1 (packed fma.rn.f32x2): dinv = rsqrt(1+deg); p[n,:] = dinv*(x[n,:]@W1)
// ---------------------------------------------------------------------------
__global__ void __launch_bounds__(256) k_gemm1(const float* __restrict__ x,
                                               const float* __restrict__ W1, int N) {
    __shared__ unsigned long long sW[128 * 16];
    const unsigned long long* Wp = (const unsigned long long*)W1;
    for (int i = threadIdx.x; i < 128 * 16; i += 256) sW[i] = Wp[i];
    __syncthreads();

    int n = blockIdx.x * 256 + threadIdx.x;
    if (n >= N) return;

    unsigned long long acc[16];
#pragma unroll
    for (int j = 0; j < 16; j++) acc[j] = 0ull;

    const float4* xr = (const float4*)(x + (size_t)n * 128);
#pragma unroll 2
    for (int k4 = 0; k4 < 32; k4++) {
        float4 xv = __ldg(&xr[k4]);
        const float* xf = (const float*)&xv;
#pragma unroll
        for (int kk = 0; kk < 4; kk++) {
            unsigned xb = __float_as_uint(xf[kk]);
            unsigned long long xx;
            asm("mov.b64 %0, {%1, %1};" : "=l"(xx) : "r"(xb));
            const unsigned long long* wr = sW + (k4 * 4 + kk) * 16;
#pragma unroll
            for (int j = 0; j < 16; j++) {
                asm("fma.rn.f32x2 %0, %1, %2, %0;"
                    : "+l"(acc[j]) : "l"(xx), "l"(wr[j]));
            }
        }
    }

    float di = rsqrtf(1.0f + (float)g_cur[n]);
    g_dinv[n] = di;
    float* out = g_p + (size_t)n * C;
#pragma unroll
    for (int j = 0; j < 16; j++) {
        unsigned lo, hi;
        asm("mov.b64 {%0, %1}, %2;" : "=r"(lo), "=r"(hi) : "l"(acc[j]));
        out[2 * j]     = __uint_as_float(lo) * di;
        out[2 * j + 1] = __uint_as_float(hi) * di;
    }
}

// ---------------------------------------------------------------------------
// Gather core: 8 threads per node, lane owns one float4 chunk; unroll 8.
// Returns dinv*sum (incl. self-loop) for this lane's chunk.
// ---------------------------------------------------------------------------
__device__ __forceinline__ float4 gather_sum(const float4* __restrict__ F,
                                             int node, int lane) {
    int deg = g_cur[node];
    int m = deg < CAP ? deg : CAP;
    const int* bp = g_bucket + (size_t)node * CAP;

    float4 a0 = __ldg(&F[(size_t)node * 8 + lane]);  // self-loop
    float4 a1 = make_float4(0, 0, 0, 0);
    float4 a2 = make_float4(0, 0, 0, 0);
    float4 a3 = make_float4(0, 0, 0, 0);

    int e = 0;
    for (; e + 8 <= m; e += 8) {
        int i0 = bp[e + 0], i1 = bp[e + 1], i2 = bp[e + 2], i3 = bp[e + 3];
        int i4 = bp[e + 4], i5 = bp[e + 5], i6 = bp[e + 6], i7 = bp[e + 7];
        float4 v0 = __ldg(&F[(size_t)i0 * 8 + lane]);
        float4 v1 = __ldg(&F[(size_t)i1 * 8 + lane]);
        float4 v2 = __ldg(&F[(size_t)i2 * 8 + lane]);
        float4 v3 = __ldg(&F[(size_t)i3 * 8 + lane]);
        float4 v4 = __ldg(&F[(size_t)i4 * 8 + lane]);
        float4 v5 = __ldg(&F[(size_t)i5 * 8 + lane]);
        float4 v6 = __ldg(&F[(size_t)i6 * 8 + lane]);
        float4 v7 = __ldg(&F[(size_t)i7 * 8 + lane]);
        a0.x += v0.x; a0.y += v0.y; a0.z += v0.z; a0.w += v0.w;
        a1.x += v1.x; a1.y += v1.y; a1.z += v1.z; a1.w += v1.w;
        a2.x += v2.x; a2.y += v2.y; a2.z += v2.z; a2.w += v2.w;
        a3.x += v3.x; a3.y += v3.y; a3.z += v3.z; a3.w += v3.w;
        a0.x += v4.x; a0.y += v4.y; a0.z += v4.z; a0.w += v4.w;
        a1.x += v5.x; a1.y += v5.y; a1.z += v5.z; a1.w += v5.w;
        a2.x += v6.x; a2.y += v6.y; a2.z += v6.z; a2.w += v6.w;
        a3.x += v7.x; a3.y += v7.y; a3.z += v7.z; a3.w += v7.w;
    }
    for (; e < m; e++) {
        int i0 = bp[e];
        float4 v0 = __ldg(&F[(size_t)i0 * 8 + lane]);
        a0.x += v0.x; a0.y += v0.y; a0.z += v0.z; a0.w += v0.w;
    }
    // exact overflow handling (normally empty)
    if (deg > CAP) {
        int oc = g_ovf_cnt;
        for (int i = 0; i < oc; i++) {
            if (g_ovf_dst[i] == node) {
                float4 v = __ldg(&F[(size_t)g_ovf_src[i] * 8 + lane]);
                a0.x += v.x; a0.y += v.y; a0.z += v.z; a0.w += v.w;
            }
        }
    }
    a0.x += a1.x + a2.x + a3.x;
    a0.y += a1.y + a2.y + a3.y;
    a0.z += a1.z + a2.z + a3.z;
    a0.w += a1.w + a2.w + a3.w;
    return a0;
}

// ---------------------------------------------------------------------------
// Gather layer 1: q = dinv*(dinv*sum + b1)
// ---------------------------------------------------------------------------
__global__ void __launch_bounds__(256) k_gather1(const float* __restrict__ b1, int N) {
    int node = blockIdx.x * 32 + (threadIdx.x >> 3);
    int lane = threadIdx.x & 7;
    if (node >= N) return;

    float4 acc = gather_sum((const float4*)g_p, node, lane);

    float di = g_dinv[node];
    float4 b = ((const float4*)b1)[lane];
    float4 q;
    q.x = di * (di * acc.x + b.x);
    q.y = di * (di * acc.y + b.y);
    q.z = di * (di * acc.z + b.z);
    q.w = di * (di * acc.w + b.w);
    ((float4*)g_q)[(size_t)node * 8 + lane] = q;
}

// ---------------------------------------------------------------------------
// Gather layer 2 + fused pooling
// ---------------------------------------------------------------------------
__device__ __forceinline__ void red_add_v4(float* ptr, float4 v) {
    asm volatile("red.global.add.v4.f32 [%0], {%1, %2, %3, %4};"
                 :: "l"(ptr), "f"(v.x), "f"(v.y), "f"(v.z), "f"(v.w)
                 : "memory");
}

__global__ void __launch_bounds__(256) k_gather2(const void* __restrict__ batch, int N) {
    int node = blockIdx.x * 32 + (threadIdx.x >> 3);
    int lane = threadIdx.x & 7;
    if (node >= N) return;

    float4 acc = gather_sum((const float4*)g_q, node, lane);

    float di = g_dinv[node];
    float4 h = make_float4(di * acc.x, di * acc.y, di * acc.z, di * acc.w);
    int gidx = idx_get(batch, node, g_flags[1]);
    red_add_v4(g_pool + (size_t)gidx * C + lane * 4, h);
}

// ---------------------------------------------------------------------------
// Head (1 block, 1 thread/graph)
// ---------------------------------------------------------------------------
__global__ void k_head(const void* __restrict__ batch, int N,
                       const float* __restrict__ W2, const float* __restrict__ b2,
                       const float* __restrict__ fcW1, const float* __restrict__ fcb1,
                       const float* __restrict__ gamma, const float* __restrict__ beta,
                       const float* __restrict__ fcW2, const float* __restrict__ fcb2,
                       float* __restrict__ out, int G) {
    __shared__ float sW2[32 * 64];
    __shared__ float sF1[64 * 32];
    __shared__ float sb2[64], sfb1[32], sgam[32], sbet[32], sfw2[32];
    __shared__ float ssum[32], ssq[32];
    __shared__ float sfb2;

    int tid = threadIdx.x;
    for (int i = tid; i < 32 * 64; i += blockDim.x) sW2[i] = W2[i];
    for (int i = tid; i < 64 * 32; i += blockDim.x) sF1[i] = fcW1[i];
    if (tid < 64) sb2[tid] = b2[tid];
    if (tid < 32) {
        sfb1[tid] = fcb1[tid]; sgam[tid] = gamma[tid]; sbet[tid] = beta[tid];
        sfw2[tid] = fcW2[tid]; ssum[tid] = 0.0f; ssq[tid] = 0.0f;
    }
    if (tid == 0) sfb2 = fcb2[0];
    __syncthreads();

    int g = tid;
    int is64 = g_flags[1];

    int lo = 0, hi = N;
    while (lo < hi) { int m = (lo + hi) >> 1; if (idx_get(batch, m, is64) < g) lo = m + 1; else hi = m; }
    int start = lo;
    hi = N;
    while (lo < hi) { int m = (lo + hi) >> 1; if (idx_get(batch, m, is64) < g + 1) lo = m + 1; else hi = m; }
    int cnt = lo - start;
    float inv_cnt = 1.0f / (float)max(cnt, 1);

    float r[32];
#pragma unroll
    for (int i = 0; i < 32; i++) r[i] = g_pool[g * 32 + i] * inv_cnt;

    float o2[64];
#pragma unroll
    for (int j = 0; j < 64; j++) o2[j] = sb2[j];
    for (int k = 0; k < 32; k++) {
        float rk = r[k];
#pragma unroll
        for (int j = 0; j < 64; j++) o2[j] = fmaf(rk, sW2[k * 64 + j], o2[j]);
    }

    float z[32];
#pragma unroll
    for (int i = 0; i < 32; i++) z[i] = sfb1[i];
    for (int j = 0; j < 64; j++) {
        float oj = o2[j];
#pragma unroll
        for (int i = 0; i < 32; i++) z[i] = fmaf(oj, sF1[j * 32 + i], z[i]);
    }
#pragma unroll
    for (int i = 0; i < 32; i++) z[i] = fmaxf(z[i], 0.0f);

    for (int i = 0; i < 32; i++) {
        float v = z[i], v2 = v * v;
#pragma unroll
        for (int o = 16; o > 0; o >>= 1) {
            v += __shfl_down_sync(0xFFFFFFFFu, v, o);
            v2 += __shfl_down_sync(0xFFFFFFFFu, v2, o);
        }
        if ((tid & 31) == 0) { atomicAdd(&ssum[i], v); atomicAdd(&ssq[i], v2); }
    }
    __syncthreads();

    float acc = sfb2;
    float invG = 1.0f / (float)G;
#pragma unroll
    for (int i = 0; i < 32; i++) {
        float mu = ssum[i] * invG;
        float var = ssq[i] * invG - mu * mu;
        float zb = (z[i] - mu) * rsqrtf(var + 1e-5f) * sgam[i] + sbet[i];
        acc = fmaf(zb, sfw2[i], acc);
    }
    out[g] = fmaxf(acc, 0.0f) + log1pf(expf(-fabsf(acc)));
}

// ---------------------------------------------------------------------------
extern "C" void kernel_launch(void* const* d_in, const int* in_sizes, int n_in,
                              void* d_out, int out_size) {
    const float* x     = (const float*)d_in[0];
    const void*  eidx  = d_in[1];
    const void*  batch = d_in[2];
    const float* W1    = (const float*)d_in[3];
    const float* b1    = (const float*)d_in[4];
    const float* W2    = (const float*)d_in[5];
    const float* b2    = (const float*)d_in[6];
    const float* fcW1  = (const float*)d_in[7];
    const float* fcb1  = (const float*)d_in[8];
    const float* gamma = (const float*)d_in[9];
    const float* beta  = (const float*)d_in[10];
    const float* fcW2  = (const float*)d_in[11];
    const float* fcb2  = (const float*)d_in[12];

    int N = in_sizes[0] / 128;
    int E = in_sizes[1] / 2;
    int G = out_size;

    k_init<<<128, 256>>>((const unsigned*)eidx, (long)2 * E,
                         (const unsigned*)batch, (long)N, N, G);
    k_place<<<ceil_div(E, 512), 256>>>(eidx, E);
    k_gemm1<<<ceil_div(N, 256), 256>>>(x, W1, N);
    k_gather1<<<ceil_div(N, 32), 256>>>(b1, N);
    k_gather2<<<ceil_div(N, 32), 256>>>(batch, N);
    k_head<<<1, G>>>(batch, N, W2, b2, fcW1, fcb1, gamma, beta, fcW2, fcb2,
                     (float*)d_out, G);
}

// round 6
// speedup vs baseline: 1.2837x; 1.0223x over previous
#include <cuda_runtime.h>
#include <cstdint>

// ---------------------------------------------------------------------------
// GCN via one-pass bucket-CSR gather:
//   place:   bucket[dst*64+slot]=src (slot via atomic); cur[dst] ends as degree
//   gemm1:   dinv=rsqrt(1+deg); p = (x @ W1) * dinv
//   gather1: q[n] = dinv*(dinv*(sum_{s in nbr(n)} p[s] + p[n]) + b1)
//   gather2: h[n] = dinv*(sum q[s] + q[n]); pool[batch[n]] += h (red.v4)
//   head:    mean, @W2+b2, relu(@fcW1+fcb1), batchnorm, softplus(@fcW2+fcb2)
// ---------------------------------------------------------------------------

#define MAXN 100000
#define MAXE 1600000
#define MAXG 256
#define C 32
#define CAP 64

__device__ int   g_bucket[MAXN * CAP];
__device__ int   g_cur[MAXN];          // placement cursor == degree afterwards
__device__ int   g_ovf_dst[MAXE];
__device__ int   g_ovf_src[MAXE];
__device__ int   g_ovf_cnt;
__device__ float g_dinv[MAXN];
__device__ float g_p[MAXN * C];
__device__ float g_q[MAXN * C];
__device__ float g_pool[MAXG * C];
__device__ int   g_flags[2];           // [0]=edge_index int64, [1]=batch int64

static inline int ceil_div(int a, int b) { return (a + b - 1) / b; }

__device__ __forceinline__ int idx_get(const void* p, long i, int is64) {
    return is64 ? (int)((const long long*)p)[i] : ((const int*)p)[i];
}

// ---------------------------------------------------------------------------
// init: zero cur/pool/ovf_cnt; block 0 detects index dtypes
// ---------------------------------------------------------------------------
__global__ void k_init(const unsigned* __restrict__ e, long ewords,
                       const unsigned* __restrict__ b, long bwords,
                       int N, int G) {
    int stride = gridDim.x * blockDim.x;
    int t = blockIdx.x * blockDim.x + threadIdx.x;
    for (int i = t; i < N; i += stride) g_cur[i] = 0;
    for (int i = t; i < G * C; i += stride) g_pool[i] = 0.0f;
    if (t == 0) g_ovf_cnt = 0;

    if (blockIdx.x == 0) {
        __shared__ unsigned se, sb;
        if (threadIdx.x == 0) { se = 0u; sb = 0u; }
        __syncthreads();
        unsigned a = 0u, c = 0u;
        long eh = ewords / 2, bh = bwords / 2;
        for (int s = 0; s < 16; s++) {
            long idx = (long)(threadIdx.x * 16 + s);
            long j = (idx * eh) / 4096;
            a |= e[2 * j + 1];
            long k = (idx * bh) / 4096;
            c |= b[2 * k + 1];
        }
        atomicOr(&se, a);
        atomicOr(&sb, c);
        __syncthreads();
        if (threadIdx.x == 0) {
            g_flags[0] = (se == 0u) ? 1 : 0;
            g_flags[1] = (sb == 0u) ? 1 : 0;
        }
    }
}

// ---------------------------------------------------------------------------
// One-pass bucket placement, 2 independent edges per thread (batched:
// loads -> atomics -> stores), full-size grid to keep >=2 waves resident.
// ---------------------------------------------------------------------------
__global__ void k_place(const void* __restrict__ eidx, int E) {
    int is64 = g_flags[0];
    int T = gridDim.x * blockDim.x;
    int tid = blockIdx.x * blockDim.x + threadIdx.x;

    int e0 = tid, e1 = tid + T;
    bool v0 = e0 < E, v1 = e1 < E;
    int s0 = 0, t0 = 0, s1 = 0, t1 = 0;
    if (v0) { s0 = idx_get(eidx, e0, is64); t0 = idx_get(eidx, (long)E + e0, is64); }
    if (v1) { s1 = idx_get(eidx, e1, is64); t1 = idx_get(eidx, (long)E + e1, is64); }

    int sl0 = 0, sl1 = 0;
    if (v0) sl0 = atomicAdd(&g_cur[t0], 1);
    if (v1) sl1 = atomicAdd(&g_cur[t1], 1);

    if (v0) {
        if (sl0 < CAP) g_bucket[(size_t)t0 * CAP + sl0] = s0;
        else { int o = atomicAdd(&g_ovf_cnt, 1); g_ovf_dst[o] = t0; g_ovf_src[o] = s0; }
    }
    if (v1) {
        if (sl1 < CAP) g_bucket[(size_t)t1 * CAP + sl1] = s1;
        else { int o = atomicAdd(&g_ovf_cnt, 1); g_ovf_dst[o] = t1; g_ovf_src[o] = s1; }
    }
}

// ---------------------------------------------------------------------------
// GEMM1 (packed fma.rn.f32x2): dinv = rsqrt(1+deg); p[n,:] = dinv*(x[n,:]@W1)
// ---------------------------------------------------------------------------
__global__ void __launch_bounds__(256) k_gemm1(const float* __restrict__ x,
                                               const float* __restrict__ W1, int N) {
    __shared__ unsigned long long sW[128 * 16];
    const unsigned long long* Wp = (const unsigned long long*)W1;
    for (int i = threadIdx.x; i < 128 * 16; i += 256) sW[i] = Wp[i];
    __syncthreads();

    int n = blockIdx.x * 256 + threadIdx.x;
    if (n >= N) return;

    unsigned long long acc[16];
#pragma unroll
    for (int j = 0; j < 16; j++) acc[j] = 0ull;

    const float4* xr = (const float4*)(x + (size_t)n * 128);
#pragma unroll 2
    for (int k4 = 0; k4 < 32; k4++) {
        float4 xv = __ldg(&xr[k4]);
        const float* xf = (const float*)&xv;
#pragma unroll
        for (int kk = 0; kk < 4; kk++) {
            unsigned xb = __float_as_uint(xf[kk]);
            unsigned long long xx;
            asm("mov.b64 %0, {%1, %1};" : "=l"(xx) : "r"(xb));
            const unsigned long long* wr = sW + (k4 * 4 + kk) * 16;
#pragma unroll
            for (int j = 0; j < 16; j++) {
                asm("fma.rn.f32x2 %0, %1, %2, %0;"
                    : "+l"(acc[j]) : "l"(xx), "l"(wr[j]));
            }
        }
    }

    float di = rsqrtf(1.0f + (float)g_cur[n]);
    g_dinv[n] = di;
    float* out = g_p + (size_t)n * C;
#pragma unroll
    for (int j = 0; j < 16; j++) {
        unsigned lo, hi;
        asm("mov.b64 {%0, %1}, %2;" : "=r"(lo), "=r"(hi) : "l"(acc[j]));
        out[2 * j]     = __uint_as_float(lo) * di;
        out[2 * j + 1] = __uint_as_float(hi) * di;
    }
}

// ---------------------------------------------------------------------------
// Gather core: 8 threads/node, lane owns one float4 chunk. Edge indices read
// as int4 (bucket rows are 256B aligned) -> 2 LDG.128 per 8 edges.
// ---------------------------------------------------------------------------
__device__ __forceinline__ float4 gather_sum(const float4* __restrict__ F,
                                             int node, int lane) {
    int deg = g_cur[node];
    int m = deg < CAP ? deg : CAP;
    const int4* bp4 = (const int4*)(g_bucket + (size_t)node * CAP);

    float4 a0 = __ldg(&F[(size_t)node * 8 + lane]);  // self-loop
    float4 a1 = make_float4(0, 0, 0, 0);
    float4 a2 = make_float4(0, 0, 0, 0);
    float4 a3 = make_float4(0, 0, 0, 0);

    int e = 0;
    for (; e + 8 <= m; e += 8) {
        int4 ia = __ldg(&bp4[e >> 2]);
        int4 ib = __ldg(&bp4[(e >> 2) + 1]);
        float4 v0 = __ldg(&F[(size_t)ia.x * 8 + lane]);
        float4 v1 = __ldg(&F[(size_t)ia.y * 8 + lane]);
        float4 v2 = __ldg(&F[(size_t)ia.z * 8 + lane]);
        float4 v3 = __ldg(&F[(size_t)ia.w * 8 + lane]);
        float4 v4 = __ldg(&F[(size_t)ib.x * 8 + lane]);
        float4 v5 = __ldg(&F[(size_t)ib.y * 8 + lane]);
        float4 v6 = __ldg(&F[(size_t)ib.z * 8 + lane]);
        float4 v7 = __ldg(&F[(size_t)ib.w * 8 + lane]);
        a0.x += v0.x; a0.y += v0.y; a0.z += v0.z; a0.w += v0.w;
        a1.x += v1.x; a1.y += v1.y; a1.z += v1.z; a1.w += v1.w;
        a2.x += v2.x; a2.y += v2.y; a2.z += v2.z; a2.w += v2.w;
        a3.x += v3.x; a3.y += v3.y; a3.z += v3.z; a3.w += v3.w;
        a0.x += v4.x; a0.y += v4.y; a0.z += v4.z; a0.w += v4.w;
        a1.x += v5.x; a1.y += v5.y; a1.z += v5.z; a1.w += v5.w;
        a2.x += v6.x; a2.y += v6.y; a2.z += v6.z; a2.w += v6.w;
        a3.x += v7.x; a3.y += v7.y; a3.z += v7.z; a3.w += v7.w;
    }
    if (e + 4 <= m) {
        int4 ia = __ldg(&bp4[e >> 2]);
        float4 v0 = __ldg(&F[(size_t)ia.x * 8 + lane]);
        float4 v1 = __ldg(&F[(size_t)ia.y * 8 + lane]);
        float4 v2 = __ldg(&F[(size_t)ia.z * 8 + lane]);
        float4 v3 = __ldg(&F[(size_t)ia.w * 8 + lane]);
        a0.x += v0.x; a0.y += v0.y; a0.z += v0.z; a0.w += v0.w;
        a1.x += v1.x; a1.y += v1.y; a1.z += v1.z; a1.w += v1.w;
        a2.x += v2.x; a2.y += v2.y; a2.z += v2.z; a2.w += v2.w;
        a3.x += v3.x; a3.y += v3.y; a3.z += v3.z; a3.w += v3.w;
        e += 4;
    }
    const int* bp = (const int*)bp4;
    for (; e < m; e++) {
        int i0 = __ldg(&bp[e]);
        float4 v0 = __ldg(&F[(size_t)i0 * 8 + lane]);
        a0.x += v0.x; a0.y += v0.y; a0.z += v0.z; a0.w += v0.w;
    }
    // exact overflow handling (normally empty)
    if (deg > CAP) {
        int oc = g_ovf_cnt;
        for (int i = 0; i < oc; i++) {
            if (g_ovf_dst[i] == node) {
                float4 v = __ldg(&F[(size_t)g_ovf_src[i] * 8 + lane]);
                a0.x += v.x; a0.y += v.y; a0.z += v.z; a0.w += v.w;
            }
        }
    }
    a0.x += a1.x + a2.x + a3.x;
    a0.y += a1.y + a2.y + a3.y;
    a0.z += a1.z + a2.z + a3.z;
    a0.w += a1.w + a2.w + a3.w;
    return a0;
}

// ---------------------------------------------------------------------------
// Gather layer 1: q = dinv*(dinv*sum + b1)
// ---------------------------------------------------------------------------
__global__ void __launch_bounds__(256) k_gather1(const float* __restrict__ b1, int N) {
    int node = blockIdx.x * 32 + (threadIdx.x >> 3);
    int lane = threadIdx.x & 7;
    if (node >= N) return;

    float4 acc = gather_sum((const float4*)g_p, node, lane);

    float di = g_dinv[node];
    float4 b = ((const float4*)b1)[lane];
    float4 q;
    q.x = di * (di * acc.x + b.x);
    q.y = di * (di * acc.y + b.y);
    q.z = di * (di * acc.z + b.z);
    q.w = di * (di * acc.w + b.w);
    ((float4*)g_q)[(size_t)node * 8 + lane] = q;
}

// ---------------------------------------------------------------------------
// Gather layer 2 + fused pooling
// ---------------------------------------------------------------------------
__device__ __forceinline__ void red_add_v4(float* ptr, float4 v) {
    asm volatile("red.global.add.v4.f32 [%0], {%1, %2, %3, %4};"
                 :: "l"(ptr), "f"(v.x), "f"(v.y), "f"(v.z), "f"(v.w)
                 : "memory");
}

__global__ void __launch_bounds__(256) k_gather2(const void* __restrict__ batch, int N) {
    int node = blockIdx.x * 32 + (threadIdx.x >> 3);
    int lane = threadIdx.x & 7;
    if (node >= N) return;

    float4 acc = gather_sum((const float4*)g_q, node, lane);

    float di = g_dinv[node];
    float4 h = make_float4(di * acc.x, di * acc.y, di * acc.z, di * acc.w);
    int gidx = idx_get(batch, node, g_flags[1]);
    red_add_v4(g_pool + (size_t)gidx * C + lane * 4, h);
}

// ---------------------------------------------------------------------------
// Head (1 block, 1 thread/graph)
// ---------------------------------------------------------------------------
__global__ void k_head(const void* __restrict__ batch, int N,
                       const float* __restrict__ W2, const float* __restrict__ b2,
                       const float* __restrict__ fcW1, const float* __restrict__ fcb1,
                       const float* __restrict__ gamma, const float* __restrict__ beta,
                       const float* __restrict__ fcW2, const float* __restrict__ fcb2,
                       float* __restrict__ out, int G) {
    __shared__ float sW2[32 * 64];
    __shared__ float sF1[64 * 32];
    __shared__ float sb2[64], sfb1[32], sgam[32], sbet[32], sfw2[32];
    __shared__ float ssum[32], ssq[32];
    __shared__ float sfb2;

    int tid = threadIdx.x;
    for (int i = tid; i < 32 * 64; i += blockDim.x) sW2[i] = W2[i];
    for (int i = tid; i < 64 * 32; i += blockDim.x) sF1[i] = fcW1[i];
    if (tid < 64) sb2[tid] = b2[tid];
    if (tid < 32) {
        sfb1[tid] = fcb1[tid]; sgam[tid] = gamma[tid]; sbet[tid] = beta[tid];
        sfw2[tid] = fcW2[tid]; ssum[tid] = 0.0f; ssq[tid] = 0.0f;
    }
    if (tid == 0) sfb2 = fcb2[0];
    __syncthreads();

    int g = tid;
    int is64 = g_flags[1];

    int lo = 0, hi = N;
    while (lo < hi) { int m = (lo + hi) >> 1; if (idx_get(batch, m, is64) < g) lo = m + 1; else hi = m; }
    int start = lo;
    hi = N;
    while (lo < hi) { int m = (lo + hi) >> 1; if (idx_get(batch, m, is64) < g + 1) lo = m + 1; else hi = m; }
    int cnt = lo - start;
    float inv_cnt = 1.0f / (float)max(cnt, 1);

    float r[32];
#pragma unroll
    for (int i = 0; i < 32; i++) r[i] = g_pool[g * 32 + i] * inv_cnt;

    float o2[64];
#pragma unroll
    for (int j = 0; j < 64; j++) o2[j] = sb2[j];
    for (int k = 0; k < 32; k++) {
        float rk = r[k];
#pragma unroll
        for (int j = 0; j < 64; j++) o2[j] = fmaf(rk, sW2[k * 64 + j], o2[j]);
    }

    float z[32];
#pragma unroll
    for (int i = 0; i < 32; i++) z[i] = sfb1[i];
    for (int j = 0; j < 64; j++) {
        float oj = o2[j];
#pragma unroll
        for (int i = 0; i < 32; i++) z[i] = fmaf(oj, sF1[j * 32 + i], z[i]);
    }
#pragma unroll
    for (int i = 0; i < 32; i++) z[i] = fmaxf(z[i], 0.0f);

    for (int i = 0; i < 32; i++) {
        float v = z[i], v2 = v * v;
#pragma unroll
        for (int o = 16; o > 0; o >>= 1) {
            v += __shfl_down_sync(0xFFFFFFFFu, v, o);
            v2 += __shfl_down_sync(0xFFFFFFFFu, v2, o);
        }
        if ((tid & 31) == 0) { atomicAdd(&ssum[i], v); atomicAdd(&ssq[i], v2); }
    }
    __syncthreads();

    float acc = sfb2;
    float invG = 1.0f / (float)G;
#pragma unroll
    for (int i = 0; i < 32; i++) {
        float mu = ssum[i] * invG;
        float var = ssq[i] * invG - mu * mu;
        float zb = (z[i] - mu) * rsqrtf(var + 1e-5f) * sgam[i] + sbet[i];
        acc = fmaf(zb, sfw2[i], acc);
    }
    out[g] = fmaxf(acc, 0.0f) + log1pf(expf(-fabsf(acc)));
}

// ---------------------------------------------------------------------------
extern "C" void kernel_launch(void* const* d_in, const int* in_sizes, int n_in,
                              void* d_out, int out_size) {
    const float* x     = (const float*)d_in[0];
    const void*  eidx  = d_in[1];
    const void*  batch = d_in[2];
    const float* W1    = (const float*)d_in[3];
    const float* b1    = (const float*)d_in[4];
    const float* W2    = (const float*)d_in[5];
    const float* b2    = (const float*)d_in[6];
    const float* fcW1  = (const float*)d_in[7];
    const float* fcb1  = (const float*)d_in[8];
    const float* gamma = (const float*)d_in[9];
    const float* beta  = (const float*)d_in[10];
    const float* fcW2  = (const float*)d_in[11];
    const float* fcb2  = (const float*)d_in[12];

    int N = in_sizes[0] / 128;
    int E = in_sizes[1] / 2;
    int G = out_size;

    k_init<<<128, 256>>>((const unsigned*)eidx, (long)2 * E,
                         (const unsigned*)batch, (long)N, N, G);
    k_place<<<ceil_div(E, 512), 256>>>(eidx, E);
    k_gemm1<<<ceil_div(N, 256), 256>>>(x, W1, N);
    k_gather1<<<ceil_div(N, 32), 256>>>(b1, N);
    k_gather2<<<ceil_div(N, 32), 256>>>(batch, N);
    k_head<<<1, G>>>(batch, N, W2, b2, fcW1, fcb1, gamma, beta, fcW2, fcb2,
                     (float*)d_out, G);
}